// round 15
// baseline (speedup 1.0000x reference)
#include <cuda_runtime.h>
#include <cuda_bf16.h>
#include <cstddef>
#include <cstdint>

#define NN    100000        // nodes
#define D1    128           // input / layer-2 output dim
#define D2    256           // hidden dim
#define EMAX  700000        // max edges (setup uses 600k)
#define NCHUNK ((NN + 1023) / 1024)

// -------- scratch (no allocation allowed; __device__ globals) --------
__device__ int   g_cnt[NN];             // in-edge counts (no self loop)
__device__ float g_dinv[NN];
__device__ int   g_off[NN + 1];         // CSR row offsets
__device__ int   g_cursor[NN];          // placement cursors
__device__ int   g_csum[NCHUNK];        // chunk sums for scan
__device__ int   g_csr[EMAX];           // CSR column (src) indices
__device__ float g_bufA[(size_t)NN * D1];   // agg1 (tf32) -> h2 (f32, in-place)
__device__ float g_W1t[D1 * D2];            // tf32-rounded weights
__device__ float g_W2t[D2 * D1];

__device__ __forceinline__ float f2tf32(float x) {
    unsigned u;
    asm("cvt.rna.tf32.f32 %0, %1;" : "=r"(u) : "f"(x));
    return __uint_as_float(u);
}

__device__ __forceinline__ void cp_async16(uint32_t smem, const void* gmem, int szbytes) {
    asm volatile("cp.async.cg.shared.global [%0], [%1], 16, %2;"
                 :: "r"(smem), "l"(gmem), "r"(szbytes));
}

__device__ __forceinline__ void mma_tf32(float* d, const unsigned* a, const unsigned* b) {
    asm volatile(
        "mma.sync.aligned.m16n8k8.row.col.f32.tf32.tf32.f32 "
        "{%0,%1,%2,%3}, {%4,%5,%6,%7}, {%8,%9}, {%0,%1,%2,%3};"
        : "+f"(d[0]), "+f"(d[1]), "+f"(d[2]), "+f"(d[3])
        : "r"(a[0]), "r"(a[1]), "r"(a[2]), "r"(a[3]), "r"(b[0]), "r"(b[1]));
}

// ---------------------------------------------------------------
// degree count
// ---------------------------------------------------------------
__global__ void k_deg_count(const int* __restrict__ dst, int E) {
    int i = blockIdx.x * blockDim.x + threadIdx.x;
    if (i >= E) return;
    int d = dst[i];
    if ((unsigned)d < NN) atomicAdd(&g_cnt[d], 1);
}

// weight pre-round to tf32 (both weights in one launch)
__global__ void k_cvt2(const float* __restrict__ W1, const float* __restrict__ W2) {
    int i = blockIdx.x * blockDim.x + threadIdx.x;
    if (i < D1 * D2)                 g_W1t[i]            = f2tf32(W1[i]);
    else if (i < 2 * D1 * D2)        g_W2t[i - D1 * D2]  = f2tf32(W2[i - D1 * D2]);
}

// ---------------------------------------------------------------
// scan phase 1: per-chunk exclusive scan of g_cnt -> g_off (+ dinv folded in)
// ---------------------------------------------------------------
__global__ __launch_bounds__(1024) void k_scan1() {
    __shared__ int sh[1024];
    int t   = threadIdx.x;
    int idx = blockIdx.x * 1024 + t;
    int v   = (idx < NN) ? g_cnt[idx] : 0;
    if (idx < NN) g_dinv[idx] = rsqrtf((float)(v + 1));   // +1 self loop
    sh[t] = v;
    __syncthreads();
    #pragma unroll
    for (int off = 1; off < 1024; off <<= 1) {
        int add = (t >= off) ? sh[t - off] : 0;
        __syncthreads();
        sh[t] += add;
        __syncthreads();
    }
    if (idx < NN) g_off[idx] = sh[t] - v;          // exclusive within chunk
    if (t == 1023) g_csum[blockIdx.x] = sh[1023];  // chunk total
}

// ---------------------------------------------------------------
// scan phase 2 (parallel fixup): tree-reduce csum[j<bid], add prefix,
// zero cursors; last block writes g_off[NN].
// ---------------------------------------------------------------
__global__ __launch_bounds__(1024) void k_scan_fix() {
    __shared__ int sh[128];
    const int bid = blockIdx.x;
    const int t   = threadIdx.x;

    if (t < 128) sh[t] = (t < NCHUNK && t < bid) ? g_csum[t] : 0;
    __syncthreads();
    #pragma unroll
    for (int s = 64; s > 0; s >>= 1) {
        if (t < s) sh[t] += sh[t + s];
        __syncthreads();
    }
    const int prefix = sh[0];

    int idx = bid * 1024 + t;
    if (idx < NN) {
        g_off[idx] += prefix;
        g_cursor[idx] = 0;
    }
    if (bid == gridDim.x - 1 && t == 0)
        g_off[NN] = prefix + g_csum[bid];          // total valid edges
}

// ---------------------------------------------------------------
// CSR placement: bucket edges by dst
// ---------------------------------------------------------------
__global__ void k_place(const int* __restrict__ srcIdx,
                        const int* __restrict__ dstIdx, int E) {
    int e = blockIdx.x * blockDim.x + threadIdx.x;
    if (e >= E) return;
    int s = srcIdx[e], d = dstIdx[e];
    if ((unsigned)s >= NN || (unsigned)d >= NN) return;
    int pos = g_off[d] + atomicAdd(&g_cursor[d], 1);
    g_csr[pos] = s;
}

// ---------------------------------------------------------------
// CSR gather: out[n,:] = dinv[n]^2*feat[n,:] + sum_e dinv[n]dinv[s]*feat[s,:]
// one warp per node; lane owns 4 dims (float4). 4x unrolled edge loop (MLP).
// ---------------------------------------------------------------
template<bool RELU, bool BIAS, bool CVT>
__global__ __launch_bounds__(256)
void k_gather(const float* __restrict__ feat, float* __restrict__ out,
              const float* __restrict__ bias) {
    int gtid = blockIdx.x * blockDim.x + threadIdx.x;
    int n    = gtid >> 5;
    int lane = gtid & 31;
    if (n >= NN) return;

    float dn = g_dinv[n];
    float4 acc = ((const float4*)(feat + (size_t)n * D1))[lane];
    float w0 = dn * dn;
    acc.x *= w0; acc.y *= w0; acc.z *= w0; acc.w *= w0;

    int e   = g_off[n];
    int end = g_off[n + 1];
    for (; e + 3 < end; e += 4) {
        int s0 = g_csr[e];
        int s1 = g_csr[e + 1];
        int s2 = g_csr[e + 2];
        int s3 = g_csr[e + 3];
        float wA = dn * g_dinv[s0];
        float wB = dn * g_dinv[s1];
        float wC = dn * g_dinv[s2];
        float wD = dn * g_dinv[s3];
        float4 v0 = ((const float4*)(feat + (size_t)s0 * D1))[lane];
        float4 v1 = ((const float4*)(feat + (size_t)s1 * D1))[lane];
        float4 v2 = ((const float4*)(feat + (size_t)s2 * D1))[lane];
        float4 v3 = ((const float4*)(feat + (size_t)s3 * D1))[lane];
        acc.x += wA * v0.x + wB * v1.x + wC * v2.x + wD * v3.x;
        acc.y += wA * v0.y + wB * v1.y + wC * v2.y + wD * v3.y;
        acc.z += wA * v0.z + wB * v1.z + wC * v2.z + wD * v3.z;
        acc.w += wA * v0.w + wB * v1.w + wC * v2.w + wD * v3.w;
    }
    for (; e < end; e++) {
        int s = g_csr[e];
        float w = dn * g_dinv[s];
        float4 v = ((const float4*)(feat + (size_t)s * D1))[lane];
        acc.x += w * v.x; acc.y += w * v.y; acc.z += w * v.z; acc.w += w * v.w;
    }

    if (BIAS) {
        float4 b = *(const float4*)(bias + lane * 4);
        acc.x += b.x; acc.y += b.y; acc.z += b.z; acc.w += b.w;
    }
    if (RELU) {
        acc.x = fmaxf(acc.x, 0.f); acc.y = fmaxf(acc.y, 0.f);
        acc.z = fmaxf(acc.z, 0.f); acc.w = fmaxf(acc.w, 0.f);
    }
    if (CVT) {
        acc.x = f2tf32(acc.x); acc.y = f2tf32(acc.y);
        acc.z = f2tf32(acc.z); acc.w = f2tf32(acc.w);
    }
    ((float4*)(out + (size_t)n * D1))[lane] = acc;
}

// ---------------------------------------------------------------
// Fused MLP: per 128-row block,
//   phase 1: C1 = tf32round(relu(A[128,128] @ W1 + b1))  -> smem [128,260]
//   phase 2: H2 = C1 @ W2 (K=256)                        -> A rows (in-place)
// 256 threads. Phase-1 warp tile 64x64 (acc 128 regs), BK=16, 2-stage.
// Phase-2 warp tile 32x64 (acc 64 regs), BK=32, 2-stage (reuses stage smem).
// ---------------------------------------------------------------
#define P1_BK   16
#define P1_APAD 20
#define P1_BPAD 260
#define P1_ASTG (128 * P1_APAD)         // 2560 floats
#define P1_BSTG (P1_BK * P1_BPAD)       // 4160 floats
#define STAGE_FLOATS (2 * P1_ASTG + 2 * P1_BSTG)   // 13440 floats
#define CSM_OFF  STAGE_FLOATS
#define CSM_PAD  260
#define CSM_FLOATS (128 * CSM_PAD)      // 33280 floats
#define FUSED_SMEM_BYTES ((STAGE_FLOATS + CSM_FLOATS) * 4)   // 186880 B

#define P2_BK   32
#define P2_BPAD 132
#define P2_BSTG (P2_BK * P2_BPAD)       // 4224 floats (fits stage region)

__global__ __launch_bounds__(256)
void fused_mlp(const float* __restrict__ A, float* __restrict__ Hout,
               const float* __restrict__ bias1)
{
    extern __shared__ float smem[];
    float* A1s[2] = { smem,                 smem + P1_ASTG };
    float* B1s[2] = { smem + 2 * P1_ASTG,   smem + 2 * P1_ASTG + P1_BSTG };
    float* B2s[2] = { smem,                 smem + P2_BSTG };   // reuse after phase 1
    float* Csm    = smem + CSM_OFF;

    const int tid  = threadIdx.x;
    const int lane = tid & 31;
    const int wid  = tid >> 5;
    const int g    = lane >> 2;
    const int t4   = lane & 3;
    const int bm   = blockIdx.x * 128;
    const float* W1 = g_W1t;
    const float* W2 = g_W2t;

    // ================= phase 1: C1 = relu(A @ W1 + b1) =================
    {
        const int wr = wid >> 2;       // 0..1 (64 rows)
        const int wc = wid & 3;        // 0..3 (64 cols)

        float acc[4][8][4];
        #pragma unroll
        for (int i = 0; i < 4; i++)
            #pragma unroll
            for (int j = 0; j < 8; j++)
                #pragma unroll
                for (int q = 0; q < 4; q++) acc[i][j][q] = 0.f;

        // A tile 128x16: 2 float4/thread ; B tile 16x256: 4 float4/thread
        const int a_r = tid >> 2;            // + p*64
        const int a_c = (tid & 3) * 4;
        const int b_r = tid >> 6;            // + p*4
        const int b_c = (tid & 63) * 4;

        auto load1 = [&](int k0, int st) {
            #pragma unroll
            for (int p = 0; p < 2; p++) {
                int r = a_r + p * 64;
                int am = bm + r;
                uint32_t dst = (uint32_t)__cvta_generic_to_shared(&A1s[st][r * P1_APAD + a_c]);
                cp_async16(dst, A + (size_t)am * D1 + k0 + a_c, (am < NN) ? 16 : 0);
            }
            #pragma unroll
            for (int p = 0; p < 4; p++) {
                int r = b_r + p * 4;
                uint32_t dst = (uint32_t)__cvta_generic_to_shared(&B1s[st][r * P1_BPAD + b_c]);
                cp_async16(dst, W1 + (size_t)(k0 + r) * D2 + b_c, 16);
            }
        };

        const int ntile = D1 / P1_BK;        // 8
        load1(0, 0);
        asm volatile("cp.async.commit_group;");

        for (int t = 0; t < ntile; t++) {
            if (t + 1 < ntile) {
                load1((t + 1) * P1_BK, (t + 1) & 1);
                asm volatile("cp.async.commit_group;");
                asm volatile("cp.async.wait_group 1;");
            } else {
                asm volatile("cp.async.wait_group 0;");
            }
            __syncthreads();

            const float* Ast = A1s[t & 1];
            const float* Bst = B1s[t & 1];
            #pragma unroll
            for (int kk = 0; kk < P1_BK; kk += 8) {
                unsigned a[4][4];
                #pragma unroll
                for (int mt = 0; mt < 4; mt++) {
                    int rb = wr * 64 + mt * 16 + g;
                    a[mt][0] = __float_as_uint(Ast[(rb    ) * P1_APAD + kk + t4    ]);
                    a[mt][1] = __float_as_uint(Ast[(rb + 8) * P1_APAD + kk + t4    ]);
                    a[mt][2] = __float_as_uint(Ast[(rb    ) * P1_APAD + kk + t4 + 4]);
                    a[mt][3] = __float_as_uint(Ast[(rb + 8) * P1_APAD + kk + t4 + 4]);
                }
                unsigned b[8][2];
                #pragma unroll
                for (int nt = 0; nt < 8; nt++) {
                    int nb = wc * 64 + nt * 8 + g;
                    b[nt][0] = __float_as_uint(Bst[(kk + t4    ) * P1_BPAD + nb]);
                    b[nt][1] = __float_as_uint(Bst[(kk + t4 + 4) * P1_BPAD + nb]);
                }
                #pragma unroll
                for (int mt = 0; mt < 4; mt++)
                    #pragma unroll
                    for (int nt = 0; nt < 8; nt++)
                        mma_tf32(acc[mt][nt], a[mt], b[nt]);
            }
            __syncthreads();
        }

        // epilogue: bias + relu + tf32 round -> Csm
        #pragma unroll
        for (int mt = 0; mt < 4; mt++) {
            #pragma unroll
            for (int nt = 0; nt < 8; nt++) {
                int col = wc * 64 + nt * 8 + 2 * t4;
                float bx = bias1[col], by = bias1[col + 1];
                int r0 = wr * 64 + mt * 16 + g;
                float2 v0;
                v0.x = f2tf32(fmaxf(acc[mt][nt][0] + bx, 0.f));
                v0.y = f2tf32(fmaxf(acc[mt][nt][1] + by, 0.f));
                *(float2*)&Csm[r0 * CSM_PAD + col] = v0;
                float2 v1;
                v1.x = f2tf32(fmaxf(acc[mt][nt][2] + bx, 0.f));
                v1.y = f2tf32(fmaxf(acc[mt][nt][3] + by, 0.f));
                *(float2*)&Csm[(r0 + 8) * CSM_PAD + col] = v1;
            }
        }
        __syncthreads();   // Csm complete; stage region free for phase 2
    }

    // ================= phase 2: H2 = Csm @ W2 (K=256) =================
    {
        const int wr = wid >> 1;       // 0..3 (32 rows)
        const int wc = wid & 1;        // 0..1 (64 cols)

        float acc[2][8][4];
        #pragma unroll
        for (int i = 0; i < 2; i++)
            #pragma unroll
            for (int j = 0; j < 8; j++)
                #pragma unroll
                for (int q = 0; q < 4; q++) acc[i][j][q] = 0.f;

        // B tile 32x128: 4 float4/thread
        const int b_r = tid >> 5;            // + p*8
        const int b_c = (tid & 31) * 4;

        auto load2 = [&](int k0, int st) {
            #pragma unroll
            for (int p = 0; p < 4; p++) {
                int r = b_r + p * 8;
                uint32_t dst = (uint32_t)__cvta_generic_to_shared(&B2s[st][r * P2_BPAD + b_c]);
                cp_async16(dst, W2 + (size_t)(k0 + r) * D1 + b_c, 16);
            }
        };

        const int ntile = D2 / P2_BK;        // 8
        load2(0, 0);
        asm volatile("cp.async.commit_group;");

        for (int t = 0; t < ntile; t++) {
            if (t + 1 < ntile) {
                load2((t + 1) * P2_BK, (t + 1) & 1);
                asm volatile("cp.async.commit_group;");
                asm volatile("cp.async.wait_group 1;");
            } else {
                asm volatile("cp.async.wait_group 0;");
            }
            __syncthreads();

            const float* Bst = B2s[t & 1];
            const int kbase = t * P2_BK;
            #pragma unroll
            for (int kk = 0; kk < P2_BK; kk += 8) {
                unsigned a[2][4];
                #pragma unroll
                for (int mt = 0; mt < 2; mt++) {
                    int rb = wr * 32 + mt * 16 + g;
                    a[mt][0] = __float_as_uint(Csm[(rb    ) * CSM_PAD + kbase + kk + t4    ]);
                    a[mt][1] = __float_as_uint(Csm[(rb + 8) * CSM_PAD + kbase + kk + t4    ]);
                    a[mt][2] = __float_as_uint(Csm[(rb    ) * CSM_PAD + kbase + kk + t4 + 4]);
                    a[mt][3] = __float_as_uint(Csm[(rb + 8) * CSM_PAD + kbase + kk + t4 + 4]);
                }
                unsigned b[8][2];
                #pragma unroll
                for (int nt = 0; nt < 8; nt++) {
                    int nb = wc * 64 + nt * 8 + g;
                    b[nt][0] = __float_as_uint(Bst[(kk + t4    ) * P2_BPAD + nb]);
                    b[nt][1] = __float_as_uint(Bst[(kk + t4 + 4) * P2_BPAD + nb]);
                }
                #pragma unroll
                for (int mt = 0; mt < 2; mt++)
                    #pragma unroll
                    for (int nt = 0; nt < 8; nt++)
                        mma_tf32(acc[mt][nt], a[mt], b[nt]);
            }
            __syncthreads();
        }

        // epilogue: write h2 (f32) in-place over A rows
        #pragma unroll
        for (int mt = 0; mt < 2; mt++) {
            #pragma unroll
            for (int nt = 0; nt < 8; nt++) {
                int col = wc * 64 + nt * 8 + 2 * t4;
                int r0 = bm + wr * 32 + mt * 16 + g;
                if (r0 < NN) {
                    float2 v = { acc[mt][nt][0], acc[mt][nt][1] };
                    *(float2*)(Hout + (size_t)r0 * D1 + col) = v;
                }
                int r1 = r0 + 8;
                if (r1 < NN) {
                    float2 v = { acc[mt][nt][2], acc[mt][nt][3] };
                    *(float2*)(Hout + (size_t)r1 * D1 + col) = v;
                }
            }
        }
    }
}

// ---------------------------------------------------------------
// launch
// ---------------------------------------------------------------
extern "C" void kernel_launch(void* const* d_in, const int* in_sizes, int n_in,
                              void* d_out, int out_size)
{
    const float* x   = (const float*)d_in[0];
    const int*   ei  = (const int*)d_in[1];      // int32 (JAX x64 disabled)
    const float* W1  = (const float*)d_in[2];
    const float* b1  = (const float*)d_in[3];
    const float* W2  = (const float*)d_in[4];
    const float* b2  = (const float*)d_in[5];
    float*       out = (float*)d_out;

    const int E = in_sizes[1] / 2;
    const int* srcIdx = ei;
    const int* dstIdx = ei + E;

    float* bufA = nullptr;  cudaGetSymbolAddress((void**)&bufA, g_bufA);
    int*   cnt  = nullptr;  cudaGetSymbolAddress((void**)&cnt, g_cnt);

    // raise dynamic smem cap for the fused kernel (host attr; capture-safe)
    cudaFuncSetAttribute(fused_mlp,
                         cudaFuncAttributeMaxDynamicSharedMemorySize, FUSED_SMEM_BYTES);

    const int T = 256;

    // 0) weight pre-round (single launch)
    k_cvt2<<<(2 * D1 * D2 + T - 1) / T, T>>>(W1, W2);

    // 1) degree + dinv + CSR build
    cudaMemsetAsync(cnt, 0, NN * sizeof(int));
    k_deg_count<<<(E + T - 1) / T, T>>>(dstIdx, E);
    k_scan1<<<NCHUNK, 1024>>>();                    // scan + dinv fused
    k_scan_fix<<<NCHUNK, 1024>>>();                 // parallel prefix fixup
    k_place<<<(E + T - 1) / T, T>>>(srcIdx, dstIdx, E);

    // 2) layer-1 aggregation (gather, tf32-rounded out): bufA = A_norm @ x
    const int gthreads = NN * 32;
    k_gather<false, false, true><<<(gthreads + T - 1) / T, T>>>(x, bufA, nullptr);

    // 3+4) fused MLP: bufA <- (relu(bufA@W1+b1)) @ W2   (in-place per row-block)
    fused_mlp<<<(NN + 127) / 128, 256, FUSED_SMEM_BYTES>>>(bufA, bufA, b1);

    // 5) layer-2 aggregation (gather) + bias + relu -> out
    k_gather<true, true, false><<<(gthreads + T - 1) / T, T>>>(bufA, out, b2);
}